// round 17
// baseline (speedup 1.0000x reference)
#include <cuda_runtime.h>
#include <math.h>

#define NB    2048
#define NC    9605
#define NL    20
#define TPB   256
#define MAXWL 2048
#define CAP   1024
#define THR   2.0f

#define ALPHA   0.5f
#define ALPHA1  0.05f
#define ALPHA2  2.0f
#define ALPHA3  10.0f

__device__ int g_mask_is_u8 = 0;   // data property -> deterministic
__device__ int g_wl_cnt;
__device__ int g_wl_packed[MAXWL];          // (class_idx << 5) | group_id
__device__ signed char g_class_group[NC];   // -1 or group id

// ---------------------------------------------------------------------------
// Prelude A: vectorized dtype detect + zero init.
// ---------------------------------------------------------------------------
__global__ void detect_kernel(const unsigned char* __restrict__ mask,
                              float* __restrict__ out) {
    const int i = blockIdx.x * blockDim.x + threadIdx.x;
    if (i == 0) { g_wl_cnt = 0; out[0] = 0.0f; }
    const int nvec = (NL * NC) / 16;
    if (i < nvec) {
        uint4 v = ((const uint4*)mask)[i];
        unsigned int chk = (v.x & 0xFFFFFF00u) | (v.y & 0xFFFFFF00u)
                         | (v.z & 0xFFFFFF00u) | (v.w & 0xFFFFFF00u);
        if (chk) atomicOr(&g_mask_is_u8, 1);
    }
    if (i == 0) {
        unsigned int wt = ((const unsigned int*)mask)[(NL * NC) / 4 - 1];
        if (wt & 0xFFFFFF00u) atomicOr(&g_mask_is_u8, 1);
    }
}

// ---------------------------------------------------------------------------
// Prelude B: build whitelist list + class->group byte map.
// ---------------------------------------------------------------------------
__global__ void build_wl_kernel(const void* __restrict__ maskv) {
    int c = blockIdx.x * blockDim.x + threadIdx.x;
    if (c >= NC) return;
    const int u8 = g_mask_is_u8;
    int g = -1;
    if (u8) {
        const unsigned char* m = (const unsigned char*)maskv;
        #pragma unroll
        for (int l = 0; l < NL; l++)
            if (m[(size_t)l * NC + c]) { g = l; break; }
    } else {
        const int* m = (const int*)maskv;
        #pragma unroll
        for (int l = 0; l < NL; l++)
            if (m[(size_t)l * NC + c] != 0) { g = l; break; }
    }
    g_class_group[c] = (signed char)g;
    if (g >= 0) {
        int pos = atomicAdd(&g_wl_cnt, 1);
        if (pos < MAXWL) g_wl_packed[pos] = (c << 5) | g;
    }
}

// ---------------------------------------------------------------------------
// Helpers
// ---------------------------------------------------------------------------
__device__ __forceinline__ unsigned int fenc(float f) {
    unsigned int u = __float_as_uint(f);
    return (u & 0x80000000u) ? ~u : (u | 0x80000000u);
}
__device__ __forceinline__ float fdec(unsigned int u) {
    return (u & 0x80000000u) ? __uint_as_float(u ^ 0x80000000u)
                             : __uint_as_float(~u);
}
__device__ __forceinline__ float sigmoidf_(float v) {
    return 1.0f / (1.0f + expf(-v));
}
__device__ __forceinline__ float rank_loss(float x1, float x2) {
    float d = x2 - x1 + ALPHA1;
    float s = 1.0f / (1.0f + expf(-ALPHA3 * d));
    return (d > 0.0f) ? (ALPHA2 * s) : s;
}

// Record positive labels from 4 consecutive words (rare branch, ~10/row).
__device__ __forceinline__ void label4(uint4 v, int base, int* flags) {
    if (v.x | v.y | v.z | v.w) {
        if (v.x) { int g = g_class_group[base    ]; if (g >= 0) flags[g] = 1; }
        if (v.y) { int g = g_class_group[base + 1]; if (g >= 0) flags[g] = 1; }
        if (v.z) { int g = g_class_group[base + 2]; if (g >= 0) flags[g] = 1; }
        if (v.w) { int g = g_class_group[base + 3]; if (g >= 0) flags[g] = 1; }
    }
}

#define TOP11_INSERT(t, v)                                   \
    if ((v) > t[10]) {                                       \
        t[10] = (v);                                         \
        _Pragma("unroll")                                    \
        for (int _j = 10; _j > 0; _j--) {                    \
            float _a = t[_j - 1], _b = t[_j];                \
            t[_j - 1] = fmaxf(_a, _b);                       \
            t[_j]     = fminf(_a, _b);                       \
        }                                                    \
    }

// ---------------------------------------------------------------------------
// One block per row.
// ---------------------------------------------------------------------------
__global__ __launch_bounds__(TPB)
void row_loss_kernel(const float* __restrict__ x,
                     const int*   __restrict__ y,
                     const int*   __restrict__ yneg,
                     float*       __restrict__ out) {
    const int b   = blockIdx.x;
    const int tid = threadIdx.x;

    __shared__ unsigned int gmax_sh[NL];
    __shared__ int   act_sh[NL];
    __shared__ int   actn_sh[NL];
    __shared__ int   ncand_sh;
    __shared__ float cand_sh[CAP];
    __shared__ float tops[32 * 11];
    __shared__ float x11_sh;

    if (tid < NL) {
        gmax_sh[tid] = fenc(-3.0e38f);
        act_sh[tid]  = 0;
        actn_sh[tid] = 0;
    }
    if (tid == 0) ncand_sh = 0;
    __syncthreads();

    const float* xr  = x    + (size_t)b * NC;
    const int*   yr  = y    + (size_t)b * NC;
    const int*   ynr = yneg + (size_t)b * NC;

    #define PUSH_CAND(v)                                     \
        if ((v) > THR) {                                     \
            int _p = atomicAdd(&ncand_sh, 1);                \
            if (_p < CAP) cand_sh[_p] = (v);                 \
        }

    const int p    = (int)(((16u - ((unsigned)(size_t)xr & 15u)) & 15u) >> 2);
    const int nvec = (NC - p) >> 2;
    const int tail = p + (nvec << 2);
    const bool al3 = ((((size_t)(yr  + p)) & 15u) == 0) &&
                     ((((size_t)(ynr + p)) & 15u) == 0);

    // Peel
    for (int c = tid; c < p; c += TPB) {
        float v = __ldg(xr + c);
        PUSH_CAND(v);
        if (__ldg(yr + c))  { int g = g_class_group[c]; if (g >= 0) act_sh[g]  = 1; }
        if (__ldg(ynr + c)) { int g = g_class_group[c]; if (g >= 0) actn_sh[g] = 1; }
    }

    const float4* xv = (const float4*)(xr + p);
    if (al3) {
        const uint4* yv4  = (const uint4*)(yr + p);
        const uint4* ynv4 = (const uint4*)(ynr + p);
        int i = tid;
        for (; i + TPB < nvec; i += 2 * TPB) {
            float4 q0 = __ldg(xv + i);
            float4 q1 = __ldg(xv + i + TPB);
            uint4  a0 = __ldg(yv4 + i);
            uint4  a1 = __ldg(yv4 + i + TPB);
            uint4  n0 = __ldg(ynv4 + i);
            uint4  n1 = __ldg(ynv4 + i + TPB);
            float m0 = fmaxf(fmaxf(q0.x, q0.y), fmaxf(q0.z, q0.w));
            float m1 = fmaxf(fmaxf(q1.x, q1.y), fmaxf(q1.z, q1.w));
            if (fmaxf(m0, m1) > THR) {
                PUSH_CAND(q0.x); PUSH_CAND(q0.y); PUSH_CAND(q0.z); PUSH_CAND(q0.w);
                PUSH_CAND(q1.x); PUSH_CAND(q1.y); PUSH_CAND(q1.z); PUSH_CAND(q1.w);
            }
            label4(a0, p + 4 * i,         act_sh);
            label4(a1, p + 4 * (i + TPB), act_sh);
            label4(n0, p + 4 * i,         actn_sh);
            label4(n1, p + 4 * (i + TPB), actn_sh);
        }
        if (i < nvec) {
            float4 q = __ldg(xv + i);
            uint4  a = __ldg(yv4 + i);
            uint4  n = __ldg(ynv4 + i);
            float m = fmaxf(fmaxf(q.x, q.y), fmaxf(q.z, q.w));
            if (m > THR) {
                PUSH_CAND(q.x); PUSH_CAND(q.y); PUSH_CAND(q.z); PUSH_CAND(q.w);
            }
            label4(a, p + 4 * i, act_sh);
            label4(n, p + 4 * i, actn_sh);
        }
    } else {
        // Fallback: x vectorized, labels scalar (correct for any alignment).
        for (int i = tid; i < nvec; i += TPB) {
            float4 q = __ldg(xv + i);
            float m = fmaxf(fmaxf(q.x, q.y), fmaxf(q.z, q.w));
            if (m > THR) {
                PUSH_CAND(q.x); PUSH_CAND(q.y); PUSH_CAND(q.z); PUSH_CAND(q.w);
            }
        }
        for (int c = p + tid; c < tail; c += TPB) {
            if (__ldg(yr + c))  { int g = g_class_group[c]; if (g >= 0) act_sh[g]  = 1; }
            if (__ldg(ynr + c)) { int g = g_class_group[c]; if (g >= 0) actn_sh[g] = 1; }
        }
    }

    // Tail
    for (int c = tail + tid; c < NC; c += TPB) {
        float v = __ldg(xr + c);
        PUSH_CAND(v);
        if (__ldg(yr + c))  { int g = g_class_group[c]; if (g >= 0) act_sh[g]  = 1; }
        if (__ldg(ynr + c)) { int g = g_class_group[c]; if (g >= 0) actn_sh[g] = 1; }
    }
    __syncthreads();

    if (tid < 32) {
        // ---- Warp 0: top-11 over candidates ------------------------------
        const int n = ncand_sh;
        float t[11];
        #pragma unroll
        for (int k = 0; k < 11; k++) t[k] = 0.0f;   // thres = sig(max(x11,0))

        if (n >= 11 && n <= CAP) {
            for (int c = tid; c < n; c += 32) {
                float v = cand_sh[c];
                TOP11_INSERT(t, v);
            }
        } else {
            for (int c = tid; c < NC; c += 32) {    // exact fallback
                float v = __ldg(xr + c);
                TOP11_INSERT(t, v);
            }
        }
        #pragma unroll
        for (int k = 0; k < 11; k++) tops[tid * 11 + k] = t[k];
        __syncwarp();

        for (int s = 16; s >= 1; s >>= 1) {
            if (tid < s) {
                float* A  = &tops[tid * 11];
                float* Bp = &tops[(tid + s) * 11];
                float outm[11];
                int a = 0, bj = 0;
                #pragma unroll
                for (int k = 0; k < 11; k++) {
                    float av = A[a], bv = Bp[bj];
                    if (av >= bv) { outm[k] = av; a++; }
                    else          { outm[k] = bv; bj++; }
                }
                #pragma unroll
                for (int k = 0; k < 11; k++) A[k] = outm[k];
            }
            __syncwarp();
        }
        if (tid == 0) x11_sh = tops[10];
    } else {
        // ---- Warps 1-7: x-only whitelist gathers (L1-hot) ----------------
        const int cnt = g_wl_cnt;
        for (int w = tid - 32; w < cnt; w += TPB - 32) {
            int pk  = g_wl_packed[w];
            float v = __ldg(xr + (pk >> 5));
            atomicMax(&gmax_sh[pk & 31], fenc(v));
        }
    }
    __syncthreads();

    // ---- Scalar epilogue --------------------------------------------------
    if (tid == 0) {
        float thres = sigmoidf_(x11_sh);

        float s_l[NL];
        int   g = -1;
        float union_max = 0.0f;
        #pragma unroll
        for (int l = 0; l < NL; l++) {
            s_l[l] = sigmoidf_(fdec(gmax_sh[l]));
            union_max = fmaxf(union_max, s_l[l]);
            if (g < 0 && act_sh[l]) g = l;
        }
        bool has_gt = (g >= 0);

        float incorrect_neg = 0.0f;
        #pragma unroll
        for (int l = 0; l < NL; l++)
            if (actn_sh[l]) incorrect_neg = fmaxf(incorrect_neg, s_l[l]);

        float loss;
        if (!has_gt) {
            loss = (1.0f - ALPHA) * rank_loss(thres, union_max)
                 + ALPHA          * rank_loss(thres, incorrect_neg);
        } else {
            float gt_max = s_l[g];
            float incorrect_max = 0.0f;
            #pragma unroll
            for (int l = 0; l < NL; l++)
                if (l != g) incorrect_max = fmaxf(incorrect_max, s_l[l]);

            loss = rank_loss(gt_max, thres);
            if (incorrect_max > 0.0f)
                loss += (1.0f - ALPHA) * rank_loss(thres, incorrect_max);
            if (incorrect_neg > 0.0f)
                loss += ALPHA * rank_loss(thres, incorrect_neg);
            else
                loss += ALPHA * rank_loss(thres, incorrect_max);
        }
        atomicAdd(out, loss);
    }
}

extern "C" void kernel_launch(void* const* d_in, const int* in_sizes, int n_in,
                              void* d_out, int out_size) {
    const float* x    = (const float*)d_in[0];
    const int*   y    = (const int*)d_in[1];
    const int*   yneg = (const int*)d_in[2];
    const void*  gmask = d_in[3];

    detect_kernel<<<(NL * NC / 16 + 255) / 256, 256>>>(
        (const unsigned char*)gmask, (float*)d_out);
    build_wl_kernel<<<(NC + 255) / 256, 256>>>(gmask);
    row_loss_kernel<<<NB, TPB>>>(x, y, yneg, (float*)d_out);
}